// round 6
// baseline (speedup 1.0000x reference)
#include <cuda_runtime.h>
#include <cuda_fp16.h>
#include <cstdint>

#define T_STEPS 512
#define BATCH   128
#define IDIM    512
#define HDIM    512
#define BH      (BATCH * HDIM)   /* 65536 */

__device__ __forceinline__ unsigned f2tf32(float f) {
    unsigned u;
    asm("cvt.rna.tf32.f32 %0, %1;" : "=r"(u) : "f"(f));
    return u;
}
__device__ __forceinline__ uint32_t pack_h2(float a, float b) {
    __half2 h = __floats2half2_rn(a, b);   // .x = a (lo), .y = b (hi)
    return *reinterpret_cast<uint32_t*>(&h);
}

__device__ __forceinline__ void mma_tf32(float c[4], const unsigned a[4],
                                         unsigned b0, unsigned b1) {
    asm volatile(
        "mma.sync.aligned.m16n8k8.row.col.f32.tf32.tf32.f32 "
        "{%0,%1,%2,%3}, {%4,%5,%6,%7}, {%8,%9}, {%0,%1,%2,%3};"
        : "+f"(c[0]), "+f"(c[1]), "+f"(c[2]), "+f"(c[3])
        : "r"(a[0]), "r"(a[1]), "r"(a[2]), "r"(a[3]), "r"(b0), "r"(b1));
}
__device__ __forceinline__ void mma_f16(float c[4], const uint32_t a[4],
                                        uint32_t b0, uint32_t b1) {
    asm volatile(
        "mma.sync.aligned.m16n8k16.row.col.f32.f16.f16.f32 "
        "{%0,%1,%2,%3}, {%4,%5,%6,%7}, {%8,%9}, {%0,%1,%2,%3};"
        : "+f"(c[0]), "+f"(c[1]), "+f"(c[2]), "+f"(c[3])
        : "r"(a[0]), "r"(a[1]), "r"(a[2]), "r"(a[3]), "r"(b0), "r"(b1));
}

__device__ __forceinline__ uint32_t smem_u32(const void* p) {
    return (uint32_t)__cvta_generic_to_shared(p);
}
__device__ __forceinline__ void cp16(uint32_t dst, const void* src) {
    asm volatile("cp.async.cg.shared.global [%0], [%1], 16;" :: "r"(dst), "l"(src));
}
__device__ __forceinline__ uint32_t mapa_rank(uint32_t addr, uint32_t rank) {
    uint32_t r;
    asm("mapa.shared::cluster.u32 %0, %1, %2;" : "=r"(r) : "r"(addr), "r"(rank));
    return r;
}
__device__ __forceinline__ void st_cluster_u32(uint32_t addr, uint32_t v) {
    asm volatile("st.shared::cluster.u32 [%0], %1;" :: "r"(addr), "r"(v) : "memory");
}
__device__ __forceinline__ void mbar_arrive_remote(uint32_t mbar) {
    asm volatile(
        "mbarrier.arrive.release.cluster.shared::cluster.b64 _, [%0];"
        :: "r"(mbar) : "memory");
}
__device__ __forceinline__ void mbar_wait_acq(uint32_t addr, uint32_t parity) {
    asm volatile(
        "{\n\t"
        ".reg .pred P;\n\t"
        "WAIT_LOOP_%=:\n\t"
        "mbarrier.try_wait.parity.acquire.cluster.shared::cta.b64 P, [%0], %1, 0x989680;\n\t"
        "@P bra.uni WAIT_DONE_%=;\n\t"
        "bra.uni WAIT_LOOP_%=;\n\t"
        "WAIT_DONE_%=:\n\t"
        "}"
        :: "r"(addr), "r"(parity) : "memory");
}

// ============================================================================
// Kernel 1: xw[t,b,:] = x[t,b,:] @ W_ih^T + bias   (unchanged, proven)
// ============================================================================
__global__ __launch_bounds__(256) void xw_gemm(const float* __restrict__ x,
                                               const float* __restrict__ w_ih,
                                               const float* __restrict__ bias,
                                               float* __restrict__ out) {
    __shared__ __align__(16) float Xs[2][128][20];
    __shared__ __align__(16) float Ws[2][64][20];

    const int tid  = threadIdx.x;
    const int warp = tid >> 5, lane = tid & 31;
    const int g = lane >> 2, tg = lane & 3;

    const int nt = blockIdx.x & 7;
    const int mt = blockIdx.x >> 3;
    const int m0 = mt * 128, n0 = nt * 64;
    const int wm = warp >> 1, wn = warp & 1;

    float c[2][4][4];
#pragma unroll
    for (int i = 0; i < 2; i++)
#pragma unroll
        for (int nb = 0; nb < 4; nb++)
#pragma unroll
            for (int r = 0; r < 4; r++) c[i][nb][r] = 0.f;

    const int xr = tid >> 2, xc = (tid & 3) * 4;
    const float* xs0  = x    + (size_t)(m0 + xr) * IDIM + xc;
    const float* xs1  = x    + (size_t)(m0 + xr + 64) * IDIM + xc;
    const float* wsrc = w_ih + (size_t)(n0 + xr) * IDIM + xc;

    const uint32_t dX0[2] = { smem_u32(&Xs[0][xr][xc]),      smem_u32(&Xs[1][xr][xc]) };
    const uint32_t dX1[2] = { smem_u32(&Xs[0][xr + 64][xc]), smem_u32(&Xs[1][xr + 64][xc]) };
    const uint32_t dW[2]  = { smem_u32(&Ws[0][xr][xc]),      smem_u32(&Ws[1][xr][xc]) };

    cp16(dX0[0], xs0);
    cp16(dX1[0], xs1);
    if (xr < 64) cp16(dW[0], wsrc);
    asm volatile("cp.async.commit_group;");

    for (int it = 0; it < 32; ++it) {
        const int s = it & 1;
        if (it < 31) {
            const int kt = (it + 1) * 16;
            cp16(dX0[s ^ 1], xs0 + kt);
            cp16(dX1[s ^ 1], xs1 + kt);
            if (xr < 64) cp16(dW[s ^ 1], wsrc + kt);
            asm volatile("cp.async.commit_group;");
            asm volatile("cp.async.wait_group 1;");
        } else {
            asm volatile("cp.async.wait_group 0;");
        }
        __syncthreads();

#pragma unroll
        for (int k8 = 0; k8 < 2; k8++) {
            const int col = k8 * 8 + tg;
            unsigned a[2][4];
#pragma unroll
            for (int i = 0; i < 2; i++) {
                int row = wm * 32 + i * 16 + g;
                a[i][0] = f2tf32(Xs[s][row][col]);
                a[i][1] = f2tf32(Xs[s][row + 8][col]);
                a[i][2] = f2tf32(Xs[s][row][col + 4]);
                a[i][3] = f2tf32(Xs[s][row + 8][col + 4]);
            }
            unsigned bf[4][2];
#pragma unroll
            for (int nb = 0; nb < 4; nb++) {
                int row = wn * 32 + nb * 8 + g;
                bf[nb][0] = f2tf32(Ws[s][row][col]);
                bf[nb][1] = f2tf32(Ws[s][row][col + 4]);
            }
#pragma unroll
            for (int i = 0; i < 2; i++)
#pragma unroll
                for (int nb = 0; nb < 4; nb++)
                    mma_tf32(c[i][nb], a[i], bf[nb][0], bf[nb][1]);
        }
        __syncthreads();
    }

#pragma unroll
    for (int i = 0; i < 2; i++)
#pragma unroll
        for (int nb = 0; nb < 4; nb++) {
            int row = m0 + wm * 32 + i * 16 + g;
            int col = n0 + wn * 32 + nb * 8 + tg * 2;
            float b0v = bias[col], b1v = bias[col + 1];
            out[(size_t)row * HDIM + col]           = c[i][nb][0] + b0v;
            out[(size_t)row * HDIM + col + 1]       = c[i][nb][1] + b1v;
            out[(size_t)(row + 8) * HDIM + col]     = c[i][nb][2] + b0v;
            out[(size_t)(row + 8) * HDIM + col + 1] = c[i][nb][3] + b1v;
        }
}

// ============================================================================
// Kernel 2: persistent recurrence, 8-CTA clusters, TWO batch groups per
// cluster interleaved per wall-step (group j+1 compute hides group j's
// exchange + sync). h exchanged as fp16x2 (1 u32/thread/rank); fp16 MMA
// (m16n8k16, fp32 accum). Hs is XOR-swizzled (col ^ row*4): conflict-free.
// Sync: full[group][buf] mbarriers, count=8, one remote arrive per producer
// CTA (tid0: fence.acq_rel.cluster after __syncthreads, then 8 arrives,
// hidden behind the other group's MMA).
// ============================================================================
__global__ __launch_bounds__(256) __cluster_dims__(8, 1, 1)
void rnn_step_kernel(const float* __restrict__ w_hh, float* __restrict__ out) {
    __shared__ uint32_t Hs[2][2][8][256];           // [group][buf][row][u32] 32KB
    __shared__ __align__(16) float Red[4][544];     // pitch 68, conflict-free
    __shared__ __align__(8) unsigned long long fullb[2][2];  // [group][buf]

    const int tid  = threadIdx.x;
    const int warp = tid >> 5, lane = tid & 31;
    const int g = lane >> 2, tg = lane & 3;
    const int cj = blockIdx.x >> 3;  // cluster 0..7 (handles batch groups 2cj, 2cj+1)
    const int i  = blockIdx.x & 7;   // rank == n-slice 0..7

    const uint32_t full_local = smem_u32(&fullb[0][0]);
    if (tid == 0) {
#pragma unroll
        for (int q = 0; q < 4; q++)
            asm volatile("mbarrier.init.shared.b64 [%0], %1;"
                         :: "r"(full_local + q * 8), "r"(8) : "memory");
        asm volatile("fence.mbarrier_init.release.cluster;" ::: "memory");
    }

    // ---- W_hh slice as fp16 m16n8k16 A-fragments (64 u32 regs) ----
    uint32_t aw[4][4][4];
#pragma unroll
    for (int nb = 0; nb < 4; nb++)
#pragma unroll
        for (int k16 = 0; k16 < 4; k16++) {
            const int r0w = i * 64 + nb * 16 + g;
            const int r1w = r0w + 8;
            const int col = warp * 64 + k16 * 16 + tg * 2;
            const float* w0 = w_hh + (size_t)r0w * HDIM + col;
            const float* w1 = w_hh + (size_t)r1w * HDIM + col;
            aw[nb][k16][0] = pack_h2(w0[0], w0[1]);
            aw[nb][k16][1] = pack_h2(w1[0], w1[1]);
            aw[nb][k16][2] = pack_h2(w0[8], w0[9]);
            aw[nb][k16][3] = pack_h2(w1[8], w1[9]);
        }

    // Ownership: thread -> (row m = warp, H cols i*64 + lane*2, +1)
    const int m = warp;
    const int n = lane * 2;
    const size_t obase0 = (size_t)(cj * 16 + m) * HDIM + i * 64 + n;      // group 0
    const size_t obase1 = (size_t)(cj * 16 + 8 + m) * HDIM + i * 64 + n;  // group 1

    // push target word (swizzled col): [m][(i*32+lane) ^ (m*4)]
    const uint32_t hs_word = (uint32_t)(m * 256 + ((i * 32 + lane) ^ (m * 4)));
    const uint32_t hs_addr0 = smem_u32(&Hs[0][0][0][0]) + hs_word * 4;

    uint32_t hpush[8], farr[8];
#pragma unroll
    for (int r = 0; r < 8; r++) {
        uint32_t rr = (i + r) & 7;
        hpush[r] = mapa_rank(hs_addr0, rr);
        farr[r]  = mapa_rank(full_local, rr);
    }

    asm volatile("barrier.cluster.arrive.aligned;" ::: "memory");
    asm volatile("barrier.cluster.wait.aligned;" ::: "memory");

    float2 xwv0 = *(const float2*)(out + obase0);
    float2 xwv1 = *(const float2*)(out + obase1);

    for (int t = 0; t < T_STEPS; t++) {
#pragma unroll
        for (int j = 0; j < 2; j++) {
            const float2 xwv = j ? xwv1 : xwv0;
            const size_t obase = j ? obase1 : obase0;
            float r0, r1;

            if (t == 0) {
                r0 = tanhf(xwv.x);
                r1 = tanhf(xwv.y);
            } else {
                const uint32_t bp  = (t - 1) & 1;
                const uint32_t par = ((t - 1) >> 1) & 1;
                mbar_wait_acq(full_local + (j * 2 + bp) * 8, par);

                const uint32_t* hb = &Hs[j][bp][0][0];
                float c[4][4];
#pragma unroll
                for (int nb = 0; nb < 4; nb++)
#pragma unroll
                    for (int r = 0; r < 4; r++) c[nb][r] = 0.f;

#pragma unroll
                for (int k16 = 0; k16 < 4; k16++) {
                    const int base = warp * 32 + k16 * 8;
                    uint32_t b0 = hb[g * 256 + ((base + tg) ^ (g * 4))];
                    uint32_t b1 = hb[g * 256 + ((base + tg + 4) ^ (g * 4))];
#pragma unroll
                    for (int nb = 0; nb < 4; nb++)
                        mma_f16(c[nb], aw[nb][k16], b0, b1);
                }

                // ---- 2-phase cross-warp K reduction ----
                if (warp >= 4) {
                    float* rp = Red[warp - 4];
#pragma unroll
                    for (int nb = 0; nb < 4; nb++)
#pragma unroll
                        for (int r = 0; r < 4; r++) {
                            int idx = (tg * 2 + (r & 1)) * 68 + nb * 16 + g + ((r & 2) << 2);
                            rp[idx] = c[nb][r];
                        }
                }
                __syncthreads();
                if (warp < 4) {
                    float* rp = Red[warp];
#pragma unroll
                    for (int nb = 0; nb < 4; nb++)
#pragma unroll
                        for (int r = 0; r < 4; r++) {
                            int idx = (tg * 2 + (r & 1)) * 68 + nb * 16 + g + ((r & 2) << 2);
                            rp[idx] += c[nb][r];
                        }
                }
                __syncthreads();

                float s0 = 0.f, s1 = 0.f;
#pragma unroll
                for (int w = 0; w < 4; w++) {
                    float2 v = *(const float2*)&Red[w][m * 68 + n];
                    s0 += v.x;
                    s1 += v.y;
                }
                r0 = tanhf(xwv.x + s0);
                r1 = tanhf(xwv.y + s1);
            }

            if (t < T_STEPS - 1) {
                // push fp16x2 slice to all 8 ranks into Hs[j][t&1]
                const uint32_t pv = pack_h2(r0, r1);
                const uint32_t boff = (uint32_t)(j * 2 + (t & 1)) * 8192u;
#pragma unroll
                for (int r = 0; r < 8; r++) st_cluster_u32(hpush[r] + boff, pv);
                __syncthreads();
                if (tid == 0) {
                    asm volatile("fence.acq_rel.cluster;" ::: "memory");
                    const uint32_t moff = (uint32_t)(j * 2 + (t & 1)) * 8u;
#pragma unroll
                    for (int r = 0; r < 8; r++) mbar_arrive_remote(farr[r] + moff);
                }
            }

            // global output + next xw prefetch (off the sync path)
            *(float2*)(out + (size_t)t * BH + obase) = make_float2(r0, r1);
            if (t == T_STEPS - 1) {
                *(float2*)(out + (size_t)T_STEPS * BH + obase) = make_float2(r0, r1);
            } else {
                float2 nx = *(const float2*)(out + (size_t)(t + 1) * BH + obase);
                if (j) xwv1 = nx; else xwv0 = nx;
            }
        }
    }

    // keep SMEM alive until every peer is done touching it
    asm volatile("barrier.cluster.arrive.aligned;" ::: "memory");
    asm volatile("barrier.cluster.wait.aligned;" ::: "memory");
}

extern "C" void kernel_launch(void* const* d_in, const int* in_sizes, int n_in,
                              void* d_out, int out_size) {
    (void)in_sizes; (void)n_in; (void)out_size;
    const float* x    = (const float*)d_in[0];
    const float* w_ih = (const float*)d_in[1];
    const float* w_hh = (const float*)d_in[2];
    const float* b    = (const float*)d_in[3];
    float* out = (float*)d_out;

    // xw = x @ W_ih^T + b  -> written into out[0 : T*B*H) (in-place workspace)
    xw_gemm<<<4096, 256>>>(x, w_ih, b, out);
    // recurrence: 8 clusters x 8 CTAs, 2 interleaved batch groups per cluster
    rnn_step_kernel<<<64, 256>>>(w_hh, out);
}

// round 8
// speedup vs baseline: 2.8906x; 2.8906x over previous
#include <cuda_runtime.h>
#include <cuda_fp16.h>
#include <cstdint>

#define T_STEPS 512
#define BATCH   128
#define IDIM    512
#define HDIM    512
#define BH      (BATCH * HDIM)   /* 65536 */

__device__ __forceinline__ unsigned f2tf32(float f) {
    unsigned u;
    asm("cvt.rna.tf32.f32 %0, %1;" : "=r"(u) : "f"(f));
    return u;
}
__device__ __forceinline__ uint32_t pack_h2(float a, float b) {
    __half2 h = __floats2half2_rn(a, b);
    return *reinterpret_cast<uint32_t*>(&h);
}
__device__ __forceinline__ float tanh_fast(float x) {
    // 1 - 2/(e^{2x}+1); saturates correctly for |x| large; ~1e-6 abs err
    float e = __expf(2.0f * x);
    return 1.0f - __fdividef(2.0f, e + 1.0f);
}

__device__ __forceinline__ void mma_tf32(float c[4], const unsigned a[4],
                                         unsigned b0, unsigned b1) {
    asm volatile(
        "mma.sync.aligned.m16n8k8.row.col.f32.tf32.tf32.f32 "
        "{%0,%1,%2,%3}, {%4,%5,%6,%7}, {%8,%9}, {%0,%1,%2,%3};"
        : "+f"(c[0]), "+f"(c[1]), "+f"(c[2]), "+f"(c[3])
        : "r"(a[0]), "r"(a[1]), "r"(a[2]), "r"(a[3]), "r"(b0), "r"(b1));
}
__device__ __forceinline__ void mma_f16(float c[4], const uint32_t a[4],
                                        uint32_t b0, uint32_t b1) {
    asm volatile(
        "mma.sync.aligned.m16n8k16.row.col.f32.f16.f16.f32 "
        "{%0,%1,%2,%3}, {%4,%5,%6,%7}, {%8,%9}, {%0,%1,%2,%3};"
        : "+f"(c[0]), "+f"(c[1]), "+f"(c[2]), "+f"(c[3])
        : "r"(a[0]), "r"(a[1]), "r"(a[2]), "r"(a[3]), "r"(b0), "r"(b1));
}

__device__ __forceinline__ uint32_t smem_u32(const void* p) {
    return (uint32_t)__cvta_generic_to_shared(p);
}
__device__ __forceinline__ void cp16(uint32_t dst, const void* src) {
    asm volatile("cp.async.cg.shared.global [%0], [%1], 16;" :: "r"(dst), "l"(src));
}
__device__ __forceinline__ uint32_t mapa_rank(uint32_t addr, uint32_t rank) {
    uint32_t r;
    asm("mapa.shared::cluster.u32 %0, %1, %2;" : "=r"(r) : "r"(addr), "r"(rank));
    return r;
}
__device__ __forceinline__ void st_cluster_u32(uint32_t addr, uint32_t v) {
    asm volatile("st.shared::cluster.u32 [%0], %1;" :: "r"(addr), "r"(v) : "memory");
}

// ============================================================================
// Kernel 1: xw[t,b,:] = x[t,b,:] @ W_ih^T + bias   (unchanged, proven)
// ============================================================================
__global__ __launch_bounds__(256) void xw_gemm(const float* __restrict__ x,
                                               const float* __restrict__ w_ih,
                                               const float* __restrict__ bias,
                                               float* __restrict__ out) {
    __shared__ __align__(16) float Xs[2][128][20];
    __shared__ __align__(16) float Ws[2][64][20];

    const int tid  = threadIdx.x;
    const int warp = tid >> 5, lane = tid & 31;
    const int g = lane >> 2, tg = lane & 3;

    const int nt = blockIdx.x & 7;
    const int mt = blockIdx.x >> 3;
    const int m0 = mt * 128, n0 = nt * 64;
    const int wm = warp >> 1, wn = warp & 1;

    float c[2][4][4];
#pragma unroll
    for (int i = 0; i < 2; i++)
#pragma unroll
        for (int nb = 0; nb < 4; nb++)
#pragma unroll
            for (int r = 0; r < 4; r++) c[i][nb][r] = 0.f;

    const int xr = tid >> 2, xc = (tid & 3) * 4;
    const float* xs0  = x    + (size_t)(m0 + xr) * IDIM + xc;
    const float* xs1  = x    + (size_t)(m0 + xr + 64) * IDIM + xc;
    const float* wsrc = w_ih + (size_t)(n0 + xr) * IDIM + xc;

    const uint32_t dX0[2] = { smem_u32(&Xs[0][xr][xc]),      smem_u32(&Xs[1][xr][xc]) };
    const uint32_t dX1[2] = { smem_u32(&Xs[0][xr + 64][xc]), smem_u32(&Xs[1][xr + 64][xc]) };
    const uint32_t dW[2]  = { smem_u32(&Ws[0][xr][xc]),      smem_u32(&Ws[1][xr][xc]) };

    cp16(dX0[0], xs0);
    cp16(dX1[0], xs1);
    if (xr < 64) cp16(dW[0], wsrc);
    asm volatile("cp.async.commit_group;");

    for (int it = 0; it < 32; ++it) {
        const int s = it & 1;
        if (it < 31) {
            const int kt = (it + 1) * 16;
            cp16(dX0[s ^ 1], xs0 + kt);
            cp16(dX1[s ^ 1], xs1 + kt);
            if (xr < 64) cp16(dW[s ^ 1], wsrc + kt);
            asm volatile("cp.async.commit_group;");
            asm volatile("cp.async.wait_group 1;");
        } else {
            asm volatile("cp.async.wait_group 0;");
        }
        __syncthreads();

#pragma unroll
        for (int k8 = 0; k8 < 2; k8++) {
            const int col = k8 * 8 + tg;
            unsigned a[2][4];
#pragma unroll
            for (int i = 0; i < 2; i++) {
                int row = wm * 32 + i * 16 + g;
                a[i][0] = f2tf32(Xs[s][row][col]);
                a[i][1] = f2tf32(Xs[s][row + 8][col]);
                a[i][2] = f2tf32(Xs[s][row][col + 4]);
                a[i][3] = f2tf32(Xs[s][row + 8][col + 4]);
            }
            unsigned bf[4][2];
#pragma unroll
            for (int nb = 0; nb < 4; nb++) {
                int row = wn * 32 + nb * 8 + g;
                bf[nb][0] = f2tf32(Ws[s][row][col]);
                bf[nb][1] = f2tf32(Ws[s][row][col + 4]);
            }
#pragma unroll
            for (int i = 0; i < 2; i++)
#pragma unroll
                for (int nb = 0; nb < 4; nb++)
                    mma_tf32(c[i][nb], a[i], bf[nb][0], bf[nb][1]);
        }
        __syncthreads();
    }

#pragma unroll
    for (int i = 0; i < 2; i++)
#pragma unroll
        for (int nb = 0; nb < 4; nb++) {
            int row = m0 + wm * 32 + i * 16 + g;
            int col = n0 + wn * 32 + nb * 8 + tg * 2;
            float b0v = bias[col], b1v = bias[col + 1];
            out[(size_t)row * HDIM + col]           = c[i][nb][0] + b0v;
            out[(size_t)row * HDIM + col + 1]       = c[i][nb][1] + b1v;
            out[(size_t)(row + 8) * HDIM + col]     = c[i][nb][2] + b0v;
            out[(size_t)(row + 8) * HDIM + col + 1] = c[i][nb][3] + b1v;
        }
}

// ============================================================================
// Kernel 2: R2 structure (proven best) + fp16 exchange/MMA + fast tanh.
// 16 clusters x 8 CTAs; CTA (j,i): batch rows j*8..+7, H cols i*64..+63.
// Per step: cluster.wait -> fp16 MMA (m16n8k16, W frags in regs) ->
// 2-phase reduce -> tanh_fast -> push fp16x2 slice to ALL 8 ranks via
// st.shared::cluster (exact R2-proven push) -> cluster.arrive.
// Double-buffered Hs.
// ============================================================================
__global__ __launch_bounds__(256) __cluster_dims__(8, 1, 1)
void rnn_step_kernel(const float* __restrict__ w_hh, float* __restrict__ out) {
    __shared__ uint32_t Hs[2][8][256];              // [buf][row][u32 col] 16KB
    __shared__ __align__(16) float Red[4][544];     // pitch 68, conflict-free

    const int tid  = threadIdx.x;
    const int warp = tid >> 5, lane = tid & 31;
    const int g = lane >> 2, tg = lane & 3;
    const int j = blockIdx.x >> 3;  // batch group 0..15
    const int i = blockIdx.x & 7;   // rank == n slice 0..7

    // ---- W_hh slice as fp16 m16n8k16 A-fragments (64 u32 regs) ----
    uint32_t aw[4][4][4];
#pragma unroll
    for (int nb = 0; nb < 4; nb++)
#pragma unroll
        for (int k16 = 0; k16 < 4; k16++) {
            const int r0w = i * 64 + nb * 16 + g;
            const int r1w = r0w + 8;
            const int col = warp * 64 + k16 * 16 + tg * 2;
            const float* w0 = w_hh + (size_t)r0w * HDIM + col;
            const float* w1 = w_hh + (size_t)r1w * HDIM + col;
            aw[nb][k16][0] = pack_h2(w0[0], w0[1]);
            aw[nb][k16][1] = pack_h2(w1[0], w1[1]);
            aw[nb][k16][2] = pack_h2(w0[8], w0[9]);
            aw[nb][k16][3] = pack_h2(w1[8], w1[9]);
        }

    // Ownership: thread -> (batch row m = warp, H cols i*64 + lane*2, +1)
    const int m = warp;
    const int n = lane * 2;
    const size_t obase = (size_t)(j * 8 + m) * HDIM + i * 64 + n;

    // push target word (swizzled col): Hs[.][m][(i*32+lane) ^ (m*4)]
    const uint32_t hs_word = (uint32_t)(m * 256 + ((i * 32 + lane) ^ (m * 4)));
    const uint32_t hs_addr0 = smem_u32(&Hs[0][0][0]) + hs_word * 4;

    uint32_t hpush[8];
#pragma unroll
    for (int r = 0; r < 8; r++) hpush[r] = mapa_rank(hs_addr0, (i + r) & 7);

    asm volatile("barrier.cluster.arrive.aligned;" ::: "memory");
    asm volatile("barrier.cluster.wait.aligned;" ::: "memory");

    float2 xwv = *(const float2*)(out + obase);  // xw[t=0]

    for (int t = 0; t < T_STEPS; t++) {
        float r0, r1;
        if (t == 0) {
            r0 = tanh_fast(xwv.x);
            r1 = tanh_fast(xwv.y);
        } else {
            asm volatile("barrier.cluster.wait.aligned;" ::: "memory");  // h_{t-1} ready
            const uint32_t* hb = &Hs[(t + 1) & 1][0][0];  // buffer (t-1)&1

            float c[4][4];
#pragma unroll
            for (int nb = 0; nb < 4; nb++)
#pragma unroll
                for (int r = 0; r < 4; r++) c[nb][r] = 0.f;

#pragma unroll
            for (int k16 = 0; k16 < 4; k16++) {
                const int base = warp * 32 + k16 * 8;
                uint32_t b0 = hb[g * 256 + ((base + tg) ^ (g * 4))];
                uint32_t b1 = hb[g * 256 + ((base + tg + 4) ^ (g * 4))];
#pragma unroll
                for (int nb = 0; nb < 4; nb++)
                    mma_f16(c[nb], aw[nb][k16], b0, b1);
            }

            // ---- 2-phase cross-warp K reduction (proven layout) ----
            if (warp >= 4) {
                float* rp = Red[warp - 4];
#pragma unroll
                for (int nb = 0; nb < 4; nb++)
#pragma unroll
                    for (int r = 0; r < 4; r++) {
                        int idx = (tg * 2 + (r & 1)) * 68 + nb * 16 + g + ((r & 2) << 2);
                        rp[idx] = c[nb][r];
                    }
            }
            __syncthreads();
            if (warp < 4) {
                float* rp = Red[warp];
#pragma unroll
                for (int nb = 0; nb < 4; nb++)
#pragma unroll
                    for (int r = 0; r < 4; r++) {
                        int idx = (tg * 2 + (r & 1)) * 68 + nb * 16 + g + ((r & 2) << 2);
                        rp[idx] += c[nb][r];
                    }
            }
            __syncthreads();

            float s0 = 0.f, s1 = 0.f;
#pragma unroll
            for (int w = 0; w < 4; w++) {
                float2 v = *(const float2*)&Red[w][m * 68 + n];
                s0 += v.x;
                s1 += v.y;
            }
            r0 = tanh_fast(xwv.x + s0);
            r1 = tanh_fast(xwv.y + s1);
        }

        if (t < T_STEPS - 1) {
            // push fp16x2 slice to all 8 ranks (R2-proven pattern), then release
            const uint32_t pv = pack_h2(r0, r1);
            const uint32_t boff = (t & 1) ? 8192u : 0u;   // bytes per Hs buffer
#pragma unroll
            for (int r = 0; r < 8; r++) st_cluster_u32(hpush[r] + boff, pv);
            asm volatile("barrier.cluster.arrive.aligned;" ::: "memory");  // release
        }

        // ---- global output (fp32) + next-step xw prefetch (in barrier slack) ----
        *(float2*)(out + (size_t)t * BH + obase) = make_float2(r0, r1);
        if (t == T_STEPS - 1) {
            *(float2*)(out + (size_t)T_STEPS * BH + obase) = make_float2(r0, r1);
        } else {
            xwv = *(const float2*)(out + (size_t)(t + 1) * BH + obase);
        }
    }

    // keep SMEM alive until every peer is done touching it
    asm volatile("barrier.cluster.arrive.aligned;" ::: "memory");
    asm volatile("barrier.cluster.wait.aligned;" ::: "memory");
}

extern "C" void kernel_launch(void* const* d_in, const int* in_sizes, int n_in,
                              void* d_out, int out_size) {
    (void)in_sizes; (void)n_in; (void)out_size;
    const float* x    = (const float*)d_in[0];
    const float* w_ih = (const float*)d_in[1];
    const float* w_hh = (const float*)d_in[2];
    const float* b    = (const float*)d_in[3];
    float* out = (float*)d_out;

    // xw = x @ W_ih^T + b  -> written into out[0 : T*B*H) (in-place workspace)
    xw_gemm<<<4096, 256>>>(x, w_ih, b, out);
    // sequential recurrence: 16 clusters of 8 CTAs, all co-resident
    rnn_step_kernel<<<128, 256>>>(w_hh, out);
}